// round 1
// baseline (speedup 1.0000x reference)
#include <cuda_runtime.h>

// out[b,k,oc,x] = sum_ci W[k,oc,ci] * in[b,ci,k,x] + bias[k,oc]
// in:  [4096,128,9,9]  w: [9,128,128]  bias: [9,128]  out: [4096,9,128,9]  (all f32)

#define CIN    128
#define COUT   128
#define KK     9
#define NB     16        // batches per block
#define NTHR   256

#define SW_STRIDE 132                       // padded oc-stride for W tile (16B-aligned rows, few conflicts)
#define SX_STRIDE 12                        // padded x-stride for X tile (LDS.128-friendly)
#define SW_WORDS (CIN * SW_STRIDE)          // 16896 floats
#define SX_WORDS (NB * CIN * SX_STRIDE)     // 24576 floats
#define SMEM_BYTES ((SW_WORDS + SX_WORDS) * 4)   // 165888 B

__device__ __forceinline__ unsigned long long pack2(float lo, float hi) {
    unsigned long long d;
    asm("mov.b64 %0, {%1, %2};" : "=l"(d) : "f"(lo), "f"(hi));
    return d;
}
__device__ __forceinline__ void unpack2(unsigned long long d, float& lo, float& hi) {
    asm("mov.b64 {%0, %1}, %2;" : "=f"(lo), "=f"(hi) : "l"(d));
}

__global__ void __launch_bounds__(NTHR, 1)
gather_vertical_kernel(const float* __restrict__ in,
                       const float* __restrict__ w,
                       const float* __restrict__ bias,
                       float* __restrict__ out)
{
    extern __shared__ float smem[];
    float* sW = smem;                 // [ci][oc] stride SW_STRIDE (transposed from gmem [oc][ci])
    float* sX = smem + SW_WORDS;      // [b_local][ci][x] stride SX_STRIDE

    const int k   = blockIdx.x;       // k fastest -> 9 k-blocks of same b-tile co-scheduled (L2 reuse)
    const int b0  = blockIdx.y * NB;
    const int tid = threadIdx.x;

    // ---- stage W[k] transposed into smem (coalesced LDG, 4-way STS conflict acceptable) ----
    const float* wk = w + k * COUT * CIN;           // [oc][ci], ci contiguous
    #pragma unroll 4
    for (int i = tid; i < COUT * CIN; i += NTHR) {
        int oc = i / CIN;
        int ci = i - oc * CIN;
        sW[ci * SW_STRIDE + oc] = wk[i];
    }

    // ---- stage X slab: in[b0..b0+15, :, k, 0..8] ----
    const float* inb = in + (long long)b0 * CIN * 81 + k * 9;
    #pragma unroll 4
    for (int i = tid; i < NB * CIN * 9; i += NTHR) {
        int x = i % 9;
        int p = i / 9;                 // p = b_local*128 + ci
        sX[p * SX_STRIDE + x] = inb[(long long)p * 81 + x];
    }
    __syncthreads();

    // ---- thread tile: 1 b_local x 8 oc x 9 x ----
    const int ocg = tid & 15;          // 0..15  (half-warp shares b_local -> x loads broadcast)
    const int bl  = tid >> 4;          // 0..15
    const int oc0 = ocg * 8;

    unsigned long long acc[9][4];      // f32x2 accumulators, init with bias
    {
        const float* bs = bias + k * COUT + oc0;
        #pragma unroll
        for (int j = 0; j < 4; j++) {
            unsigned long long bp = pack2(bs[2 * j], bs[2 * j + 1]);
            #pragma unroll
            for (int x = 0; x < 9; x++) acc[x][j] = bp;
        }
    }

    const float* xbase = sX + bl * CIN * SX_STRIDE;
    const float* wbase = sW + oc0;

    #pragma unroll 2
    for (int ci = 0; ci < CIN; ci++) {
        const float4* xv = reinterpret_cast<const float4*>(xbase + ci * SX_STRIDE);
        float4 v0 = xv[0];
        float4 v1 = xv[1];
        float  v8 = (xbase + ci * SX_STRIDE)[8];

        const float4* wv = reinterpret_cast<const float4*>(wbase + ci * SW_STRIDE);
        float4 w0 = wv[0];
        float4 w1 = wv[1];
        unsigned long long wp0 = pack2(w0.x, w0.y);
        unsigned long long wp1 = pack2(w0.z, w0.w);
        unsigned long long wp2 = pack2(w1.x, w1.y);
        unsigned long long wp3 = pack2(w1.z, w1.w);

        float xs[9] = {v0.x, v0.y, v0.z, v0.w, v1.x, v1.y, v1.z, v1.w, v8};
        #pragma unroll
        for (int x = 0; x < 9; x++) {
            unsigned long long xp = pack2(xs[x], xs[x]);
            asm("fma.rn.f32x2 %0, %1, %2, %0;" : "+l"(acc[x][0]) : "l"(xp), "l"(wp0));
            asm("fma.rn.f32x2 %0, %1, %2, %0;" : "+l"(acc[x][1]) : "l"(xp), "l"(wp1));
            asm("fma.rn.f32x2 %0, %1, %2, %0;" : "+l"(acc[x][2]) : "l"(xp), "l"(wp2));
            asm("fma.rn.f32x2 %0, %1, %2, %0;" : "+l"(acc[x][3]) : "l"(xp), "l"(wp3));
        }
    }

    __syncthreads();   // done reading sX; reuse it as output staging

    // ---- stage outputs to smem: sOut[b_local][oc][x] (contiguous 1152 floats per b) ----
    float* sOut = sX;
    #pragma unroll
    for (int x = 0; x < 9; x++) {
        #pragma unroll
        for (int j = 0; j < 4; j++) {
            float lo, hi;
            unpack2(acc[x][j], lo, hi);
            sOut[bl * 1152 + (oc0 + 2 * j)     * 9 + x] = lo;
            sOut[bl * 1152 + (oc0 + 2 * j + 1) * 9 + x] = hi;
        }
    }
    __syncthreads();

    // ---- coalesced float4 copy to gmem: per b, region out[(b*9+k)*1152 ..] is contiguous ----
    float4*       og = reinterpret_cast<float4*>(out);
    const float4* sv = reinterpret_cast<const float4*>(sOut);
    #pragma unroll 4
    for (int i = tid; i < NB * 288; i += NTHR) {
        int blc = i / 288;
        int r   = i - blc * 288;
        og[((long long)(b0 + blc) * 9 + k) * 288 + r] = sv[blc * 288 + r];
    }
}

extern "C" void kernel_launch(void* const* d_in, const int* in_sizes, int n_in,
                              void* d_out, int out_size)
{
    const float* in   = (const float*)d_in[0];   // [B,128,9,9]
    const float* w    = (const float*)d_in[1];   // [9,128,128]
    const float* bias = (const float*)d_in[2];   // [9,128]
    float* out        = (float*)d_out;           // [B,9,128,9]

    int B = in_sizes[0] / (CIN * 81);            // 4096

    static int attr_set = 0;  // attribute call is idempotent & deterministic
    cudaFuncSetAttribute(gather_vertical_kernel,
                         cudaFuncAttributeMaxDynamicSharedMemorySize, SMEM_BYTES);
    (void)attr_set;

    dim3 grid(KK, B / NB);
    gather_vertical_kernel<<<grid, NTHR, SMEM_BYTES>>>(in, w, bias, out);
}

// round 2
// speedup vs baseline: 1.4399x; 1.4399x over previous
#include <cuda_runtime.h>

// out[b,k,oc,x] = sum_ci W[k,oc,ci] * in[b,ci,k,x] + bias[k,oc]
// in: [4096,128,9,9]  w: [9,128,128]  bias: [9,128]  out: [4096,9,128,9] (f32)

#define CIN    128
#define COUT   128
#define KK     9
#define NB     8         // batches per block
#define NTHR   256

#define SW_STRIDE 132    // padded oc-stride for W tile: 528B rows, 16B-aligned, 4-way staging conflict only
#define SX_STRIDE 10     // x-stride for X tile: 40B rows, 8B-aligned (LDS.64 pairs)
#define SW_WORDS (CIN * SW_STRIDE)            // 16896 floats = 67584 B
#define SX_WORDS (NB * CIN * SX_STRIDE)       // 10240 floats = 40960 B
#define SMEM_BYTES ((SW_WORDS + SX_WORDS) * 4)  // 108544 B -> 2 CTAs/SM

__device__ __forceinline__ unsigned long long pack2(float lo, float hi) {
    unsigned long long d;
    asm("mov.b64 %0, {%1, %2};" : "=l"(d) : "f"(lo), "f"(hi));
    return d;
}
__device__ __forceinline__ void unpack2(unsigned long long d, float& lo, float& hi) {
    asm("mov.b64 {%0, %1}, %2;" : "=f"(lo), "=f"(hi) : "l"(d));
}

__global__ void __launch_bounds__(NTHR, 2)
gather_vertical_kernel(const float* __restrict__ in,
                       const float* __restrict__ w,
                       const float* __restrict__ bias,
                       float* __restrict__ out)
{
    extern __shared__ float smem[];
    float* sW = smem;                 // [ci][oc], stride SW_STRIDE (transposed from gmem [oc][ci])
    float* sX = smem + SW_WORDS;      // [b_local*128+ci][x], stride SX_STRIDE

    const int k   = blockIdx.x;       // k fastest: 9 k-blocks of one b-tile co-resident -> L2 sector dedup
    const int b0  = blockIdx.y * NB;
    const int tid = threadIdx.x;

    // ---- stage W[k] transposed: coalesced LDG, 4-way STS bank conflict (one-time) ----
    const float* wk = w + k * COUT * CIN;      // [oc][ci], ci contiguous
    #pragma unroll 4
    for (int i = tid; i < COUT * CIN; i += NTHR) {
        int oc = i >> 7;
        int ci = i & 127;
        sW[ci * SW_STRIDE + oc] = wk[i];
    }

    // ---- stage X slab: in[b0..b0+7, :, k, 0..8] ----
    const float* inb = in + (long long)b0 * CIN * 81 + k * 9;
    #pragma unroll 4
    for (int i = tid; i < NB * CIN * 9; i += NTHR) {
        int x = i % 9;
        int p = i / 9;                 // p = b_local*128 + ci
        sX[p * SX_STRIDE + x] = inb[(long long)p * 81 + x];
    }
    __syncthreads();

    // ---- thread tile: 1 b_local x 4 oc x 9 x ----
    const int ocg = tid & 31;          // warp spans all 128 oc; whole warp shares b_local
    const int bl  = tid >> 5;          // 0..7 == warp id
    const int oc0 = ocg * 4;

    unsigned long long acc[9][2];      // f32x2 accumulators over oc-pairs, init with bias
    {
        const float* bs = bias + k * COUT + oc0;
        unsigned long long bp0 = pack2(bs[0], bs[1]);
        unsigned long long bp1 = pack2(bs[2], bs[3]);
        #pragma unroll
        for (int x = 0; x < 9; x++) { acc[x][0] = bp0; acc[x][1] = bp1; }
    }

    const float* xrow = sX + bl * CIN * SX_STRIDE;
    const float* wrow = sW + oc0;

    #pragma unroll 4
    for (int ci = 0; ci < CIN; ci++) {
        // X: 9 scalars for this (b,ci) row — broadcast to all 32 lanes
        float2 x01 = *reinterpret_cast<const float2*>(xrow + 0);
        float2 x23 = *reinterpret_cast<const float2*>(xrow + 2);
        float2 x45 = *reinterpret_cast<const float2*>(xrow + 4);
        float2 x67 = *reinterpret_cast<const float2*>(xrow + 6);
        float  x8  = xrow[8];

        // W: 4 floats, loaded as 2 pre-packed f32x2 operands (no movs)
        ulonglong2 wp = *reinterpret_cast<const ulonglong2*>(wrow);

        float xs[9] = {x01.x, x01.y, x23.x, x23.y, x45.x, x45.y, x67.x, x67.y, x8};
        #pragma unroll
        for (int x = 0; x < 9; x++) {
            unsigned long long xp = pack2(xs[x], xs[x]);
            asm("fma.rn.f32x2 %0, %1, %2, %0;" : "+l"(acc[x][0]) : "l"(xp), "l"(wp.x));
            asm("fma.rn.f32x2 %0, %1, %2, %0;" : "+l"(acc[x][1]) : "l"(xp), "l"(wp.y));
        }
        xrow += SX_STRIDE;
        wrow += SW_STRIDE;
    }

    __syncthreads();   // done reading sX; reuse as output staging

    // ---- stage outputs: sOut[b_local][oc][x], contiguous 1152 floats per b ----
    float* sOut = sX;
    #pragma unroll
    for (int x = 0; x < 9; x++) {
        #pragma unroll
        for (int j = 0; j < 2; j++) {
            float lo, hi;
            unpack2(acc[x][j], lo, hi);
            sOut[bl * 1152 + (oc0 + 2 * j)     * 9 + x] = lo;
            sOut[bl * 1152 + (oc0 + 2 * j + 1) * 9 + x] = hi;
        }
    }
    __syncthreads();

    // ---- coalesced float4 stores: out[(b*9+k)*1152 ..] contiguous per b ----
    float4*       og = reinterpret_cast<float4*>(out);
    const float4* sv = reinterpret_cast<const float4*>(sOut);
    #pragma unroll
    for (int i = tid; i < NB * 288; i += NTHR) {
        int blc = i / 288;
        int r   = i - blc * 288;
        og[((long long)(b0 + blc) * 9 + k) * 288 + r] = sv[blc * 288 + r];
    }
}

extern "C" void kernel_launch(void* const* d_in, const int* in_sizes, int n_in,
                              void* d_out, int out_size)
{
    const float* in   = (const float*)d_in[0];   // [B,128,9,9]
    const float* w    = (const float*)d_in[1];   // [9,128,128]
    const float* bias = (const float*)d_in[2];   // [9,128]
    float* out        = (float*)d_out;           // [B,9,128,9]

    int B = in_sizes[0] / (CIN * 81);            // 4096

    cudaFuncSetAttribute(gather_vertical_kernel,
                         cudaFuncAttributeMaxDynamicSharedMemorySize, SMEM_BYTES);

    dim3 grid(KK, B / NB);
    gather_vertical_kernel<<<grid, NTHR, SMEM_BYTES>>>(in, w, bias, out);
}